// round 1
// baseline (speedup 1.0000x reference)
#include <cuda_runtime.h>
#include <math_constants.h>

// Problem constants (fixed by the dataset)
#define Bb 4
#define Hh 512
#define Ww 512
#define Cc 32
#define HO 256
#define WO 256
#define NPIX (Bb*Hh*Ww)          // 1,048,576 pixels
#define MASK_WORDS (NPIX/32)     // 32,768

// Scratch: uninitialized dense grid guarded by an occupancy bitmask.
// (128 MB + 128 KB __device__ globals — the sanctioned no-alloc scratch path.)
__device__ float    g_dense[(size_t)NPIX * Cc];
__device__ unsigned g_mask[MASK_WORDS];

__global__ void clear_mask_kernel() {
    int i = blockIdx.x * blockDim.x + threadIdx.x;
    if (i < MASK_WORDS) g_mask[i] = 0u;
}

// 8 threads per point; each moves one float4 (4 channels). Lane 0 sets the bit.
__global__ void scatter_kernel(const float* __restrict__ feat,
                               const int*   __restrict__ coors,
                               int n_pts) {
    int t = blockIdx.x * blockDim.x + threadIdx.x;
    int n = t >> 3;
    int j = t & 7;
    if (n >= n_pts) return;
    int b = coors[n * 3 + 0];
    int y = coors[n * 3 + 1];
    int x = coors[n * 3 + 2];
    int p = (b * Hh + y) * Ww + x;
    float4 v = reinterpret_cast<const float4*>(feat)[(size_t)n * 8 + j];
    reinterpret_cast<float4*>(g_dense)[(size_t)p * 8 + j] = v;
    if (j == 0) atomicOr(&g_mask[p >> 5], 1u << (p & 31));
}

// One 8-thread group per output pixel; leader computes 9-bit presence, shfl-broadcast,
// then float4 max over the present neighbors only.
__global__ void pool_kernel(float* __restrict__ out) {
    int t     = blockIdx.x * blockDim.x + threadIdx.x;
    int gid   = t >> 3;               // output pixel id, exact grid (no bounds check)
    int lane8 = t & 7;                // channel chunk (4 channels each)

    int xo = gid & (WO - 1);
    int yo = (gid >> 8) & (HO - 1);
    int b  = gid >> 16;

    int yi0 = 2 * yo - 1;
    int xi0 = 2 * xo - 1;

    unsigned pres = 0u;
    int laneId = threadIdx.x & 31;
    if ((laneId & 7) == 0) {
        #pragma unroll
        for (int ky = 0; ky < 3; ky++) {
            int yi = yi0 + ky;
            if ((unsigned)yi < (unsigned)Hh) {
                int rowbase = (b * Hh + yi) * Ww;
                #pragma unroll
                for (int kx = 0; kx < 3; kx++) {
                    int xi = xi0 + kx;
                    if ((unsigned)xi < (unsigned)Ww) {
                        int idx = rowbase + xi;
                        if ((g_mask[idx >> 5] >> (idx & 31)) & 1u)
                            pres |= 1u << (ky * 3 + kx);
                    }
                }
            }
        }
    }
    pres = __shfl_sync(0xffffffffu, pres, laneId & 24);

    float4 acc = make_float4(-CUDART_INF_F, -CUDART_INF_F, -CUDART_INF_F, -CUDART_INF_F);
    #pragma unroll
    for (int ky = 0; ky < 3; ky++) {
        #pragma unroll
        for (int kx = 0; kx < 3; kx++) {
            if (pres & (1u << (ky * 3 + kx))) {
                int idx = (b * Hh + (yi0 + ky)) * Ww + (xi0 + kx);
                float4 v = reinterpret_cast<const float4*>(g_dense)[(size_t)idx * 8 + lane8];
                acc.x = fmaxf(acc.x, v.x);
                acc.y = fmaxf(acc.y, v.y);
                acc.z = fmaxf(acc.z, v.z);
                acc.w = fmaxf(acc.w, v.w);
            }
        }
    }

    float4 o = pres ? acc : make_float4(0.f, 0.f, 0.f, 0.f);
    reinterpret_cast<float4*>(out)[(size_t)gid * 8 + lane8] = o;
}

extern "C" void kernel_launch(void* const* d_in, const int* in_sizes, int n_in,
                              void* d_out, int out_size) {
    const float* feat  = (const float*)d_in[0];
    const int*   coors = (const int*)d_in[1];
    (void)n_in; (void)out_size;

    int n_pts = in_sizes[0] / Cc;   // 300000

    // 1) clear occupancy bitmask (tiny)
    clear_mask_kernel<<<(MASK_WORDS + 255) / 256, 256>>>();

    // 2) scatter features into dense scratch + set bits
    {
        int threads = n_pts * 8;
        int blocks  = (threads + 255) / 256;
        scatter_kernel<<<blocks, 256>>>(feat, coors, n_pts);
    }

    // 3) masked 3x3/s2 max-pool into output
    {
        int total  = Bb * HO * WO * 8;        // 2,097,152 threads
        int blocks = total / 256;             // 8192 (exact)
        pool_kernel<<<blocks, 256>>>((float*)d_out);
    }
}

// round 2
// speedup vs baseline: 1.5148x; 1.5148x over previous
#include <cuda_runtime.h>
#include <math_constants.h>

// Problem constants (fixed by the dataset)
#define Bb 4
#define Hh 512
#define Ww 512
#define Cc 32
#define HO 256
#define WO 256
#define NPIX (Bb*Hh*Ww)          // 1,048,576 pixels

// Per-pixel slot: 0 = empty, else (point_index + 1).  4 MB __device__ scratch.
__device__ int g_slot[NPIX];

__global__ void clear_slot_kernel() {
    int i = blockIdx.x * blockDim.x + threadIdx.x;   // 262144 threads, 16B each
    reinterpret_cast<uint4*>(g_slot)[i] = make_uint4(0u, 0u, 0u, 0u);
}

// One thread per point: plain store of (n+1) — coords are unique, no atomics.
__global__ void scatter_kernel(const int* __restrict__ coors, int n_pts) {
    int n = blockIdx.x * blockDim.x + threadIdx.x;
    if (n >= n_pts) return;
    int b = coors[n * 3 + 0];
    int y = coors[n * 3 + 1];
    int x = coors[n * 3 + 2];
    g_slot[(b * Hh + y) * Ww + x] = n + 1;
}

// 8 threads per output pixel (4 channels each as float4). Each thread probes the
// 9 neighbor slots (warp-broadcast loads) and gathers features straight from the
// L2-resident input array.
__global__ void __launch_bounds__(256) pool_kernel(const float* __restrict__ feat,
                                                   float* __restrict__ out) {
    int t     = blockIdx.x * blockDim.x + threadIdx.x;
    int gid   = t >> 3;               // output pixel id (exact grid, no bounds check)
    int lane8 = t & 7;                // channel chunk: 4 floats

    int xo = gid & (WO - 1);
    int yo = (gid >> 8) & (HO - 1);
    int b  = gid >> 16;

    int yi0 = 2 * yo - 1;
    int xi0 = 2 * xo - 1;

    float4 acc = make_float4(-CUDART_INF_F, -CUDART_INF_F, -CUDART_INF_F, -CUDART_INF_F);
    bool any = false;

    #pragma unroll
    for (int ky = 0; ky < 3; ky++) {
        int yi = yi0 + ky;
        if ((unsigned)yi < (unsigned)Hh) {
            int rowbase = (b * Hh + yi) * Ww;
            #pragma unroll
            for (int kx = 0; kx < 3; kx++) {
                int xi = xi0 + kx;
                if ((unsigned)xi < (unsigned)Ww) {
                    int s = __ldg(&g_slot[rowbase + xi]);
                    if (s) {
                        any = true;
                        float4 v = reinterpret_cast<const float4*>(feat)[(size_t)(s - 1) * 8 + lane8];
                        acc.x = fmaxf(acc.x, v.x);
                        acc.y = fmaxf(acc.y, v.y);
                        acc.z = fmaxf(acc.z, v.z);
                        acc.w = fmaxf(acc.w, v.w);
                    }
                }
            }
        }
    }

    float4 o = any ? acc : make_float4(0.f, 0.f, 0.f, 0.f);
    reinterpret_cast<float4*>(out)[(size_t)gid * 8 + lane8] = o;
}

extern "C" void kernel_launch(void* const* d_in, const int* in_sizes, int n_in,
                              void* d_out, int out_size) {
    const float* feat  = (const float*)d_in[0];
    const int*   coors = (const int*)d_in[1];
    (void)n_in; (void)out_size;

    int n_pts = in_sizes[0] / Cc;   // 300000

    // 1) clear slot map (4 MB, vectorized)
    clear_slot_kernel<<<(NPIX / 4) / 256, 256>>>();

    // 2) scatter point indices (4 B per point, no atomics)
    scatter_kernel<<<(n_pts + 255) / 256, 256>>>(coors, n_pts);

    // 3) masked 3x3/s2 max-pool, gathering features from the input array
    {
        int total  = Bb * HO * WO * 8;        // 2,097,152 threads
        pool_kernel<<<total / 256, 256>>>(feat, (float*)d_out);
    }
}

// round 3
// speedup vs baseline: 1.7844x; 1.1780x over previous
#include <cuda_runtime.h>
#include <math_constants.h>

// Problem constants (fixed by the dataset)
#define Bb 4
#define Hh 512
#define Ww 512
#define Cc 32
#define HO 256
#define WO 256
#define HP 514                   // padded height (1-pixel halo)
#define WP 514                   // padded width
#define NPAD (Bb*HP*WP)          // 1,056,784 padded pixels

// Per-pixel slot over the PADDED grid: 0 = empty, else (point_index + 1).
// Borders stay zero forever (cleared every call, never scattered to).
__device__ int g_slot[NPAD];

__global__ void clear_slot_kernel() {
    int i = blockIdx.x * blockDim.x + threadIdx.x;
    if (i < NPAD / 4) reinterpret_cast<uint4*>(g_slot)[i] = make_uint4(0u, 0u, 0u, 0u);
}

// One thread per point: plain store of (n+1) — coords are unique, no atomics.
__global__ void scatter_kernel(const int* __restrict__ coors, int n_pts) {
    int n = blockIdx.x * blockDim.x + threadIdx.x;
    if (n >= n_pts) return;
    int b = coors[n * 3 + 0];
    int y = coors[n * 3 + 1];
    int x = coors[n * 3 + 2];
    g_slot[(b * HP + (y + 1)) * WP + (x + 1)] = n + 1;
}

// 8 threads per output pixel (4 channels each as float4).
// Padded slot map -> 9 unconditional front-batched probes (MLP=9),
// then predicated feature gathers straight from the L2-resident input.
__global__ void __launch_bounds__(256) pool_kernel(const float* __restrict__ feat,
                                                   float* __restrict__ out) {
    int t     = blockIdx.x * blockDim.x + threadIdx.x;
    int gid   = t >> 3;               // output pixel id (exact grid)
    int lane8 = t & 7;                // channel chunk: 4 floats

    int xo = gid & (WO - 1);
    int yo = (gid >> 8) & (HO - 1);
    int b  = gid >> 16;

    // window top-left in padded coords: (2*yo, 2*xo)
    const int* __restrict__ sp = g_slot + ((b * HP + 2 * yo) * WP + 2 * xo);

    // 9 independent probes — compiler front-batches these
    int s0 = __ldg(sp);
    int s1 = __ldg(sp + 1);
    int s2 = __ldg(sp + 2);
    int s3 = __ldg(sp + WP);
    int s4 = __ldg(sp + WP + 1);
    int s5 = __ldg(sp + WP + 2);
    int s6 = __ldg(sp + 2 * WP);
    int s7 = __ldg(sp + 2 * WP + 1);
    int s8 = __ldg(sp + 2 * WP + 2);

    int any = s0 | s1 | s2 | s3 | s4 | s5 | s6 | s7 | s8;

    float4 acc = make_float4(-CUDART_INF_F, -CUDART_INF_F, -CUDART_INF_F, -CUDART_INF_F);
    const float4* __restrict__ f4 = reinterpret_cast<const float4*>(feat);

    #define GATHER(S)                                                            \
        if (S) {                                                                 \
            float4 v = f4[(size_t)((S) - 1) * 8 + lane8];                        \
            acc.x = fmaxf(acc.x, v.x); acc.y = fmaxf(acc.y, v.y);                \
            acc.z = fmaxf(acc.z, v.z); acc.w = fmaxf(acc.w, v.w);                \
        }
    GATHER(s0) GATHER(s1) GATHER(s2)
    GATHER(s3) GATHER(s4) GATHER(s5)
    GATHER(s6) GATHER(s7) GATHER(s8)
    #undef GATHER

    float4 o = any ? acc : make_float4(0.f, 0.f, 0.f, 0.f);
    reinterpret_cast<float4*>(out)[(size_t)gid * 8 + lane8] = o;
}

extern "C" void kernel_launch(void* const* d_in, const int* in_sizes, int n_in,
                              void* d_out, int out_size) {
    const float* feat  = (const float*)d_in[0];
    const int*   coors = (const int*)d_in[1];
    (void)n_in; (void)out_size;

    int n_pts = in_sizes[0] / Cc;   // 300000

    // 1) clear padded slot map (~4 MB, vectorized)
    clear_slot_kernel<<<((NPAD / 4) + 255) / 256, 256>>>();

    // 2) scatter point indices (4 B per point, no atomics)
    scatter_kernel<<<(n_pts + 255) / 256, 256>>>(coors, n_pts);

    // 3) branch-free-probe 3x3/s2 max-pool, gathering features from the input
    {
        int total = Bb * HO * WO * 8;         // 2,097,152 threads
        pool_kernel<<<total / 256, 256>>>(feat, (float*)d_out);
    }
}